// round 1
// baseline (speedup 1.0000x reference)
#include <cuda_runtime.h>
#include <math.h>
#include <float.h>

#define NN 100000
#define EE 1600000
#define TT 4
#define NLOCK 15
#define ETOT (EE + NN)
#define TN (TT * NN)

// ---------------- static device scratch (no allocations allowed) ----------------
__device__ float    g_x[TN * 12];       // layer input features (padded to 12)
__device__ float    g_h[TN * 12];       // projected features
__device__ float    g_es[TN * 2];       // per-node source logit part (2 heads)
__device__ float    g_ed[TN * 2];       // per-node dest logit part
__device__ unsigned g_m[TN * 2];        // segment max, stored as order-flipped uint
__device__ float    g_numer[TN * 12];   // softmax-weighted sum accumulator
__device__ float    g_denom[TN * 2];    // softmax denominator accumulator
__device__ double   g_sum[TT];
__device__ double   g_sumsq[TT];
__device__ float    g_stats[TT * 2];    // mean, rstd per timestep

// ---------------- helpers ----------------
__device__ __forceinline__ unsigned flipf(float f) {
    unsigned u = __float_as_uint(f);
    return u ^ ((u >> 31) ? 0xFFFFFFFFu : 0x80000000u);
}
__device__ __forceinline__ float unflipf(unsigned u) {
    return __uint_as_float(u ^ ((u >> 31) ? 0x80000000u : 0xFFFFFFFFu));
}
__device__ __forceinline__ void red_add_v4(float* p, float4 v) {
    asm volatile("red.global.add.v4.f32 [%0], {%1,%2,%3,%4};"
                 :: "l"(p), "f"(v.x), "f"(v.y), "f"(v.z), "f"(v.w) : "memory");
}
__device__ __forceinline__ void red_add_v2(float* p, float2 v) {
    asm volatile("red.global.add.v2.f32 [%0], {%1,%2};"
                 :: "l"(p), "f"(v.x), "f"(v.y) : "memory");
}
__device__ __forceinline__ float lrelu(float x) { return x > 0.f ? x : 0.2f * x; }

// ---------------- stats: mean/std (ddof=1) of requests[t, 15:] ----------------
__global__ void zero_stats_kernel() {
    int i = threadIdx.x;
    if (i < TT) { g_sum[i] = 0.0; g_sumsq[i] = 0.0; }
}

__global__ void reduce_req_kernel(const float* __restrict__ req) {
    const int t = blockIdx.y;
    const int M = NN - NLOCK;
    double s = 0.0, ss = 0.0;
    for (int i = blockIdx.x * blockDim.x + threadIdx.x; i < M; i += gridDim.x * blockDim.x) {
        double v = (double)req[t * NN + NLOCK + i];
        s += v; ss += v * v;
    }
    #pragma unroll
    for (int o = 16; o > 0; o >>= 1) {
        s  += __shfl_down_sync(0xFFFFFFFFu, s,  o);
        ss += __shfl_down_sync(0xFFFFFFFFu, ss, o);
    }
    __shared__ double shs[8], shss[8];
    int w = threadIdx.x >> 5, l = threadIdx.x & 31;
    if (l == 0) { shs[w] = s; shss[w] = ss; }
    __syncthreads();
    if (threadIdx.x == 0) {
        double S = 0.0, SS = 0.0;
        int nw = blockDim.x >> 5;
        for (int i = 0; i < nw; i++) { S += shs[i]; SS += shss[i]; }
        atomicAdd(&g_sum[t], S);
        atomicAdd(&g_sumsq[t], SS);
    }
}

__global__ void finalize_stats_kernel() {
    int t = threadIdx.x;
    if (t < TT) {
        double n = (double)(NN - NLOCK);
        double mean = g_sum[t] / n;
        double var = (g_sumsq[t] - g_sum[t] * mean) / (n - 1.0);
        g_stats[2 * t]     = (float)mean;
        g_stats[2 * t + 1] = (float)(1.0 / sqrt(var));
    }
}

// ---------------- build layer-0 input x = [emb[nt], req_f, ti] ----------------
__global__ void build_x_kernel(const int* __restrict__ nt,
                               const float* __restrict__ req,
                               const float* __restrict__ ti,
                               const float* __restrict__ emb) {
    int idx = blockIdx.x * blockDim.x + threadIdx.x;
    if (idx >= TN) return;
    int t = idx / NN;
    int n = idx - t * NN;
    float mean = g_stats[2 * t], rstd = g_stats[2 * t + 1];
    int type = nt[idx];
    float r = req[idx];
    float rf = (n < NLOCK) ? r : (r - mean) * rstd;
    float* x = &g_x[idx * 12];
    x[0] = __ldg(&emb[type * 3 + 0]);
    x[1] = __ldg(&emb[type * 3 + 1]);
    x[2] = __ldg(&emb[type * 3 + 2]);
    x[3] = rf;
    x[4] = ti[idx];
}

// ---------------- per-node: h = x@W, e_s, e_d; init accumulators ----------------
template <int DIN>
__global__ void node_kernel(const float* __restrict__ W,
                            const float* __restrict__ as_,
                            const float* __restrict__ ad_) {
    __shared__ float sW[DIN * 12];
    __shared__ float sas[12], sad[12];
    for (int i = threadIdx.x; i < DIN * 12; i += blockDim.x) sW[i] = W[i];
    if (threadIdx.x < 12) { sas[threadIdx.x] = as_[threadIdx.x]; sad[threadIdx.x] = ad_[threadIdx.x]; }
    __syncthreads();
    int idx = blockIdx.x * blockDim.x + threadIdx.x;
    if (idx >= TN) return;

    float xv[DIN];
    const float* xp = &g_x[idx * 12];
    #pragma unroll
    for (int k = 0; k < DIN; k++) xv[k] = xp[k];

    float h[12];
    #pragma unroll
    for (int j = 0; j < 12; j++) {
        float a = 0.f;
        #pragma unroll
        for (int k = 0; k < DIN; k++) a = fmaf(xv[k], sW[k * 12 + j], a);
        h[j] = a;
    }
    float4* hp = (float4*)&g_h[idx * 12];
    hp[0] = make_float4(h[0], h[1], h[2],  h[3]);
    hp[1] = make_float4(h[4], h[5], h[6],  h[7]);
    hp[2] = make_float4(h[8], h[9], h[10], h[11]);

    float es0 = 0.f, es1 = 0.f, ed0 = 0.f, ed1 = 0.f;
    #pragma unroll
    for (int c = 0; c < 6; c++) {
        es0 = fmaf(h[c],     sas[c],     es0);
        es1 = fmaf(h[6 + c], sas[6 + c], es1);
        ed0 = fmaf(h[c],     sad[c],     ed0);
        ed1 = fmaf(h[6 + c], sad[6 + c], ed1);
    }
    *(float2*)&g_es[idx * 2] = make_float2(es0, es1);
    *(float2*)&g_ed[idx * 2] = make_float2(ed0, ed1);
    *(uint2*)&g_m[idx * 2]   = make_uint2(0u, 0u);   // flipped -NaN sentinel: below everything
    *(float2*)&g_denom[idx * 2] = make_float2(0.f, 0.f);
    float4 z = make_float4(0.f, 0.f, 0.f, 0.f);
    float4* np = (float4*)&g_numer[idx * 12];
    np[0] = z; np[1] = z; np[2] = z;
}

// ---------------- edge pass 1: segment max of logits over dst ----------------
__global__ void edge_max_kernel(const int* __restrict__ ei) {
    int gid = blockIdx.x * blockDim.x + threadIdx.x;
    if (gid >= TT * ETOT) return;
    int t = gid / ETOT;
    int e = gid - t * ETOT;
    int src, dst;
    if (e < EE) {
        const int* base = ei + (size_t)t * (2 * EE);
        src = __ldg(base + e);
        dst = __ldg(base + EE + e);
    } else {
        src = dst = e - EE;
    }
    int ns = t * NN + src, nd = t * NN + dst;
    float2 es = *(const float2*)&g_es[ns * 2];
    float2 ed = *(const float2*)&g_ed[nd * 2];
    unsigned f0 = flipf(lrelu(es.x + ed.x));
    unsigned f1 = flipf(lrelu(es.y + ed.y));
    unsigned* mp = &g_m[nd * 2];
    if (f0 > mp[0]) atomicMax(mp, f0);        // monotonic: stale read only over-triggers
    if (f1 > mp[1]) atomicMax(mp + 1, f1);
}

// ---------------- edge pass 2: accumulate numerator + denominator ----------------
__global__ void edge_acc_kernel(const int* __restrict__ ei) {
    int gid = blockIdx.x * blockDim.x + threadIdx.x;
    if (gid >= TT * ETOT) return;
    int t = gid / ETOT;
    int e = gid - t * ETOT;
    int src, dst;
    if (e < EE) {
        const int* base = ei + (size_t)t * (2 * EE);
        src = __ldg(base + e);
        dst = __ldg(base + EE + e);
    } else {
        src = dst = e - EE;
    }
    int ns = t * NN + src, nd = t * NN + dst;
    float2 es = *(const float2*)&g_es[ns * 2];
    float2 ed = *(const float2*)&g_ed[nd * 2];
    float l0 = lrelu(es.x + ed.x);
    float l1 = lrelu(es.y + ed.y);
    uint2 mu = *(const uint2*)&g_m[nd * 2];
    float p0 = __expf(l0 - unflipf(mu.x));
    float p1 = __expf(l1 - unflipf(mu.y));

    red_add_v2(&g_denom[nd * 2], make_float2(p0, p1));

    const float4* hp = (const float4*)&g_h[ns * 12];
    float4 h0 = hp[0], h1 = hp[1], h2 = hp[2];
    float* np = &g_numer[nd * 12];
    red_add_v4(np,     make_float4(h0.x * p0, h0.y * p0, h0.z * p0, h0.w * p0));
    red_add_v4(np + 4, make_float4(h1.x * p0, h1.y * p0, h1.z * p1, h1.w * p1));
    red_add_v4(np + 8, make_float4(h2.x * p1, h2.y * p1, h2.z * p1, h2.w * p1));
}

// ---------------- finalize: out = numer/denom + b (+ relu) ----------------
template <bool RELU, bool TO_OUT>
__global__ void finalize_kernel(const float* __restrict__ b, float* __restrict__ outp) {
    __shared__ float sb[12];
    if (threadIdx.x < 12) sb[threadIdx.x] = b[threadIdx.x];
    __syncthreads();
    int idx = blockIdx.x * blockDim.x + threadIdx.x;
    if (idx >= TN) return;
    float2 d = *(const float2*)&g_denom[idx * 2];
    float r0 = 1.f / (d.x + 1e-16f);
    float r1 = 1.f / (d.y + 1e-16f);
    const float4* np = (const float4*)&g_numer[idx * 12];
    float4 n0 = np[0], n1 = np[1], n2 = np[2];
    float o[12];
    o[0]  = n0.x * r0 + sb[0];  o[1]  = n0.y * r0 + sb[1];
    o[2]  = n0.z * r0 + sb[2];  o[3]  = n0.w * r0 + sb[3];
    o[4]  = n1.x * r0 + sb[4];  o[5]  = n1.y * r0 + sb[5];
    o[6]  = n1.z * r1 + sb[6];  o[7]  = n1.w * r1 + sb[7];
    o[8]  = n2.x * r1 + sb[8];  o[9]  = n2.y * r1 + sb[9];
    o[10] = n2.z * r1 + sb[10]; o[11] = n2.w * r1 + sb[11];
    if (RELU) {
        #pragma unroll
        for (int j = 0; j < 12; j++) o[j] = fmaxf(o[j], 0.f);
    }
    float* dstp = TO_OUT ? (outp + (size_t)idx * 12) : &g_x[idx * 12];
    float4* dp = (float4*)dstp;
    dp[0] = make_float4(o[0], o[1], o[2],  o[3]);
    dp[1] = make_float4(o[4], o[5], o[6],  o[7]);
    dp[2] = make_float4(o[8], o[9], o[10], o[11]);
}

// ---------------- launch ----------------
extern "C" void kernel_launch(void* const* d_in, const int* in_sizes, int n_in,
                              void* d_out, int out_size) {
    const int*   node_types = (const int*)d_in[0];
    const float* requests   = (const float*)d_in[1];
    const float* time_index = (const float*)d_in[2];
    const int*   edge_index = (const int*)d_in[3];
    const float* emb        = (const float*)d_in[4];
    float* out = (float*)d_out;

    const int BT = 256;
    const int node_blocks = (TN + BT - 1) / BT;
    const int edge_blocks = (TT * ETOT + BT - 1) / BT;

    zero_stats_kernel<<<1, 32>>>();
    {
        dim3 grid(128, TT);
        reduce_req_kernel<<<grid, BT>>>(requests);
    }
    finalize_stats_kernel<<<1, 32>>>();
    build_x_kernel<<<node_blocks, BT>>>(node_types, requests, time_index, emb);

    for (int i = 0; i < 4; i++) {
        const float* W  = (const float*)d_in[5 + 4 * i + 0];
        const float* as = (const float*)d_in[5 + 4 * i + 1];
        const float* ad = (const float*)d_in[5 + 4 * i + 2];
        const float* b  = (const float*)d_in[5 + 4 * i + 3];

        if (i == 0) node_kernel<5><<<node_blocks, BT>>>(W, as, ad);
        else        node_kernel<12><<<node_blocks, BT>>>(W, as, ad);

        edge_max_kernel<<<edge_blocks, BT>>>(edge_index);
        edge_acc_kernel<<<edge_blocks, BT>>>(edge_index);

        if (i < 3) finalize_kernel<true,  false><<<node_blocks, BT>>>(b, nullptr);
        else       finalize_kernel<false, true ><<<node_blocks, BT>>>(b, out);
    }
}

// round 2
// speedup vs baseline: 1.5677x; 1.5677x over previous
#include <cuda_runtime.h>
#include <math.h>

#define NN 100000
#define EE 1600000
#define TT 4
#define NLOCK 15
#define ETOT (EE + NN)
#define TN (TT * NN)

// ---------------- static device scratch ----------------
// Per-node packed row (64B): [es0, es1, ed0, ed1, h0..h11]
__device__ float4 g_hs[TN * 4];
// Per-node accumulator row (64B): [numer0..11, den0, den1, pad, pad]
__device__ float4 g_acc[TN * 4];
__device__ double g_sum[TT];
__device__ double g_sumsq[TT];
__device__ float  g_stats[TT * 2];   // mean, rstd per timestep

// ---------------- helpers ----------------
__device__ __forceinline__ void red_add_v4(float* p, float a, float b, float c, float d) {
    asm volatile("red.global.add.v4.f32 [%0], {%1,%2,%3,%4};"
                 :: "l"(p), "f"(a), "f"(b), "f"(c), "f"(d) : "memory");
}
__device__ __forceinline__ void red_add_v2(float* p, float a, float b) {
    asm volatile("red.global.add.v2.f32 [%0], {%1,%2};"
                 :: "l"(p), "f"(a), "f"(b) : "memory");
}
__device__ __forceinline__ float lrelu(float x) { return x > 0.f ? x : 0.2f * x; }

// ---------------- stats: mean/std (ddof=1) of requests[t, 15:] ----------------
__global__ void zero_stats_kernel() {
    int i = threadIdx.x;
    if (i < TT) { g_sum[i] = 0.0; g_sumsq[i] = 0.0; }
}

__global__ void reduce_req_kernel(const float* __restrict__ req) {
    const int t = blockIdx.y;
    const int M = NN - NLOCK;
    double s = 0.0, ss = 0.0;
    for (int i = blockIdx.x * blockDim.x + threadIdx.x; i < M; i += gridDim.x * blockDim.x) {
        double v = (double)req[t * NN + NLOCK + i];
        s += v; ss += v * v;
    }
    #pragma unroll
    for (int o = 16; o > 0; o >>= 1) {
        s  += __shfl_down_sync(0xFFFFFFFFu, s,  o);
        ss += __shfl_down_sync(0xFFFFFFFFu, ss, o);
    }
    __shared__ double shs[8], shss[8];
    int w = threadIdx.x >> 5, l = threadIdx.x & 31;
    if (l == 0) { shs[w] = s; shss[w] = ss; }
    __syncthreads();
    if (threadIdx.x == 0) {
        double S = 0.0, SS = 0.0;
        int nw = blockDim.x >> 5;
        for (int i = 0; i < nw; i++) { S += shs[i]; SS += shss[i]; }
        atomicAdd(&g_sum[t], S);
        atomicAdd(&g_sumsq[t], SS);
    }
}

__global__ void finalize_stats_kernel() {
    int t = threadIdx.x;
    if (t < TT) {
        double n = (double)(NN - NLOCK);
        double mean = g_sum[t] / n;
        double var = (g_sumsq[t] - g_sum[t] * mean) / (n - 1.0);
        g_stats[2 * t]     = (float)mean;
        g_stats[2 * t + 1] = (float)(1.0 / sqrt(var));
    }
}

// ---------------- shared projection: h = x@W, es/ed, write row, zero acc ----------------
template <int DIN>
__device__ __forceinline__ void project_and_store(int idx, const float* xv,
                                                  const float* sW,
                                                  const float* sas, const float* sad) {
    float h[12];
    #pragma unroll
    for (int j = 0; j < 12; j++) {
        float a = 0.f;
        #pragma unroll
        for (int k = 0; k < DIN; k++) a = fmaf(xv[k], sW[k * 12 + j], a);
        h[j] = a;
    }
    float es0 = 0.f, es1 = 0.f, ed0 = 0.f, ed1 = 0.f;
    #pragma unroll
    for (int c = 0; c < 6; c++) {
        es0 = fmaf(h[c],     sas[c],     es0);
        es1 = fmaf(h[6 + c], sas[6 + c], es1);
        ed0 = fmaf(h[c],     sad[c],     ed0);
        ed1 = fmaf(h[6 + c], sad[6 + c], ed1);
    }
    float4* row = &g_hs[idx * 4];
    row[0] = make_float4(es0, es1, ed0, ed1);
    row[1] = make_float4(h[0], h[1], h[2],  h[3]);
    row[2] = make_float4(h[4], h[5], h[6],  h[7]);
    row[3] = make_float4(h[8], h[9], h[10], h[11]);
    float4 z = make_float4(0.f, 0.f, 0.f, 0.f);
    float4* acc = &g_acc[idx * 4];
    acc[0] = z; acc[1] = z; acc[2] = z; acc[3] = z;
}

// ---------------- layer 0: build x from inputs, project ----------------
__global__ void node0_kernel(const int* __restrict__ nt,
                             const float* __restrict__ req,
                             const float* __restrict__ ti,
                             const float* __restrict__ emb,
                             const float* __restrict__ W,
                             const float* __restrict__ as_,
                             const float* __restrict__ ad_) {
    __shared__ float sW[5 * 12];
    __shared__ float sas[12], sad[12];
    for (int i = threadIdx.x; i < 5 * 12; i += blockDim.x) sW[i] = W[i];
    if (threadIdx.x < 12) { sas[threadIdx.x] = as_[threadIdx.x]; sad[threadIdx.x] = ad_[threadIdx.x]; }
    __syncthreads();
    int idx = blockIdx.x * blockDim.x + threadIdx.x;
    if (idx >= TN) return;
    int t = idx / NN;
    int n = idx - t * NN;
    float mean = g_stats[2 * t], rstd = g_stats[2 * t + 1];
    int type = nt[idx];
    float r = req[idx];
    float xv[5];
    xv[0] = __ldg(&emb[type * 3 + 0]);
    xv[1] = __ldg(&emb[type * 3 + 1]);
    xv[2] = __ldg(&emb[type * 3 + 2]);
    xv[3] = (n < NLOCK) ? r : (r - mean) * rstd;
    xv[4] = ti[idx];
    project_and_store<5>(idx, xv, sW, sas, sad);
}

// ---------------- layers 1..3: finalize prev layer (relu) + project ----------------
__global__ void node_mid_kernel(const float* __restrict__ b_prev,
                                const float* __restrict__ W,
                                const float* __restrict__ as_,
                                const float* __restrict__ ad_) {
    __shared__ float sW[12 * 12];
    __shared__ float sas[12], sad[12], sb[12];
    for (int i = threadIdx.x; i < 12 * 12; i += blockDim.x) sW[i] = W[i];
    if (threadIdx.x < 12) {
        sas[threadIdx.x] = as_[threadIdx.x];
        sad[threadIdx.x] = ad_[threadIdx.x];
        sb[threadIdx.x]  = b_prev[threadIdx.x];
    }
    __syncthreads();
    int idx = blockIdx.x * blockDim.x + threadIdx.x;
    if (idx >= TN) return;
    const float4* acc = &g_acc[idx * 4];
    float4 n0 = acc[0], n1 = acc[1], n2 = acc[2], dd = acc[3];
    float r0 = 1.f / (dd.x + 1e-16f);
    float r1 = 1.f / (dd.y + 1e-16f);
    float xv[12];
    xv[0]  = fmaxf(n0.x * r0 + sb[0],  0.f);
    xv[1]  = fmaxf(n0.y * r0 + sb[1],  0.f);
    xv[2]  = fmaxf(n0.z * r0 + sb[2],  0.f);
    xv[3]  = fmaxf(n0.w * r0 + sb[3],  0.f);
    xv[4]  = fmaxf(n1.x * r0 + sb[4],  0.f);
    xv[5]  = fmaxf(n1.y * r0 + sb[5],  0.f);
    xv[6]  = fmaxf(n1.z * r1 + sb[6],  0.f);
    xv[7]  = fmaxf(n1.w * r1 + sb[7],  0.f);
    xv[8]  = fmaxf(n2.x * r1 + sb[8],  0.f);
    xv[9]  = fmaxf(n2.y * r1 + sb[9],  0.f);
    xv[10] = fmaxf(n2.z * r1 + sb[10], 0.f);
    xv[11] = fmaxf(n2.w * r1 + sb[11], 0.f);
    project_and_store<12>(idx, xv, sW, sas, sad);
}

// ---------------- single edge pass: p = exp(lrelu(es+ed)); accumulate ----------------
__global__ void edge_kernel(const int* __restrict__ ei) {
    const int t = blockIdx.y;
    int e = blockIdx.x * blockDim.x + threadIdx.x;
    if (e >= ETOT) return;
    int src, dst;
    if (e < EE) {
        const int* base = ei + (size_t)t * (2 * EE);
        src = __ldg(base + e);
        dst = __ldg(base + EE + e);
    } else {
        src = dst = e - EE;
    }
    const float4* rs = &g_hs[(size_t)(t * NN + src) * 4];
    const float4* rd = &g_hs[(size_t)(t * NN + dst) * 4];
    float4 s0 = rs[0];             // es0, es1 in .x,.y
    float4 d0 = rd[0];             // ed0, ed1 in .z,.w
    float p0 = __expf(lrelu(s0.x + d0.z));
    float p1 = __expf(lrelu(s0.y + d0.w));
    float4 h0 = rs[1], h1 = rs[2], h2 = rs[3];
    float* acc = (float*)&g_acc[(size_t)(t * NN + dst) * 4];
    red_add_v4(acc,     h0.x * p0, h0.y * p0, h0.z * p0, h0.w * p0);
    red_add_v4(acc + 4, h1.x * p0, h1.y * p0, h1.z * p1, h1.w * p1);
    red_add_v4(acc + 8, h2.x * p1, h2.y * p1, h2.z * p1, h2.w * p1);
    red_add_v2(acc + 12, p0, p1);
}

// ---------------- final output: out = numer/denom + b (no relu) ----------------
__global__ void final_kernel(const float* __restrict__ b, float* __restrict__ outp) {
    __shared__ float sb[12];
    if (threadIdx.x < 12) sb[threadIdx.x] = b[threadIdx.x];
    __syncthreads();
    int idx = blockIdx.x * blockDim.x + threadIdx.x;
    if (idx >= TN) return;
    const float4* acc = &g_acc[idx * 4];
    float4 n0 = acc[0], n1 = acc[1], n2 = acc[2], dd = acc[3];
    float r0 = 1.f / (dd.x + 1e-16f);
    float r1 = 1.f / (dd.y + 1e-16f);
    float4* dp = (float4*)(outp + (size_t)idx * 12);
    dp[0] = make_float4(n0.x * r0 + sb[0], n0.y * r0 + sb[1],
                        n0.z * r0 + sb[2], n0.w * r0 + sb[3]);
    dp[1] = make_float4(n1.x * r0 + sb[4], n1.y * r0 + sb[5],
                        n1.z * r1 + sb[6], n1.w * r1 + sb[7]);
    dp[2] = make_float4(n2.x * r1 + sb[8], n2.y * r1 + sb[9],
                        n2.z * r1 + sb[10], n2.w * r1 + sb[11]);
}

// ---------------- launch ----------------
extern "C" void kernel_launch(void* const* d_in, const int* in_sizes, int n_in,
                              void* d_out, int out_size) {
    const int*   node_types = (const int*)d_in[0];
    const float* requests   = (const float*)d_in[1];
    const float* time_index = (const float*)d_in[2];
    const int*   edge_index = (const int*)d_in[3];
    const float* emb        = (const float*)d_in[4];
    float* out = (float*)d_out;

    const int BT = 256;
    const int node_blocks = (TN + BT - 1) / BT;
    dim3 edge_grid((ETOT + BT - 1) / BT, TT);

    zero_stats_kernel<<<1, 32>>>();
    {
        dim3 grid(128, TT);
        reduce_req_kernel<<<grid, BT>>>(requests);
    }
    finalize_stats_kernel<<<1, 32>>>();

    // layer 0
    node0_kernel<<<node_blocks, BT>>>(node_types, requests, time_index, emb,
                                      (const float*)d_in[5], (const float*)d_in[6],
                                      (const float*)d_in[7]);
    edge_kernel<<<edge_grid, BT>>>(edge_index);

    // layers 1..3
    for (int i = 1; i < 4; i++) {
        const float* b_prev = (const float*)d_in[5 + 4 * (i - 1) + 3];
        const float* W  = (const float*)d_in[5 + 4 * i + 0];
        const float* as = (const float*)d_in[5 + 4 * i + 1];
        const float* ad = (const float*)d_in[5 + 4 * i + 2];
        node_mid_kernel<<<node_blocks, BT>>>(b_prev, W, as, ad);
        edge_kernel<<<edge_grid, BT>>>(edge_index);
    }

    final_kernel<<<node_blocks, BT>>>((const float*)d_in[5 + 12 + 3], out);
}

// round 3
// speedup vs baseline: 2.3664x; 1.5094x over previous
#include <cuda_runtime.h>
#include <math.h>

#define NN 100000
#define EE 1600000
#define TT 4
#define NLOCK 15
#define TN (TT * NN)
#define NBLK 391          // ceil(TN / 1024)

// ---------------- static device scratch ----------------
// Per-node packed row (64B): [es0, es1, ed0, ed1, h0..h11]
__device__ float4 g_hsA[TN * 4];
__device__ float4 g_hsB[TN * 4];
__device__ int    g_cnt[TN];        // per-(t,node) in-degree (real edges only)
__device__ int    g_off[TN];        // global exclusive scan of g_cnt
__device__ int    g_cur[TN];        // scatter cursor
__device__ int    g_bsum[512];
__device__ int    g_csr[TT * EE];   // src indices sorted by (t, dst)
__device__ double g_sum[TT];
__device__ double g_sumsq[TT];
__device__ float  g_stats[TT * 2];  // mean, rstd per timestep

__device__ __forceinline__ float lrelu(float x) { return x > 0.f ? x : 0.2f * x; }

// ---------------- stats: mean/std (ddof=1) of requests[t, 15:] ----------------
__global__ void zero_stats_kernel() {
    int i = threadIdx.x;
    if (i < TT) { g_sum[i] = 0.0; g_sumsq[i] = 0.0; }
}

__global__ void reduce_req_kernel(const float* __restrict__ req) {
    const int t = blockIdx.y;
    const int M = NN - NLOCK;
    double s = 0.0, ss = 0.0;
    for (int i = blockIdx.x * blockDim.x + threadIdx.x; i < M; i += gridDim.x * blockDim.x) {
        double v = (double)req[t * NN + NLOCK + i];
        s += v; ss += v * v;
    }
    #pragma unroll
    for (int o = 16; o > 0; o >>= 1) {
        s  += __shfl_down_sync(0xFFFFFFFFu, s,  o);
        ss += __shfl_down_sync(0xFFFFFFFFu, ss, o);
    }
    __shared__ double shs[8], shss[8];
    int w = threadIdx.x >> 5, l = threadIdx.x & 31;
    if (l == 0) { shs[w] = s; shss[w] = ss; }
    __syncthreads();
    if (threadIdx.x == 0) {
        double S = 0.0, SS = 0.0;
        int nw = blockDim.x >> 5;
        for (int i = 0; i < nw; i++) { S += shs[i]; SS += shss[i]; }
        atomicAdd(&g_sum[t], S);
        atomicAdd(&g_sumsq[t], SS);
    }
}

__global__ void finalize_stats_kernel() {
    int t = threadIdx.x;
    if (t < TT) {
        double n = (double)(NN - NLOCK);
        double mean = g_sum[t] / n;
        double var = (g_sumsq[t] - g_sum[t] * mean) / (n - 1.0);
        g_stats[2 * t]     = (float)mean;
        g_stats[2 * t + 1] = (float)(1.0 / sqrt(var));
    }
}

// ---------------- CSR build ----------------
__global__ void zero_cnt_kernel() {
    int i = blockIdx.x * blockDim.x + threadIdx.x;
    if (i < TN) g_cnt[i] = 0;
}

__global__ void hist_kernel(const int* __restrict__ ei) {
    int e = blockIdx.x * blockDim.x + threadIdx.x;
    int t = blockIdx.y;
    if (e >= EE) return;
    int dst = __ldg(ei + (size_t)t * 2 * EE + EE + e);
    atomicAdd(&g_cnt[t * NN + dst], 1);
}

__global__ void scan1_kernel() {   // 1024 threads, 1024 elems per block
    __shared__ int s[1024];
    int idx = blockIdx.x * 1024 + threadIdx.x;
    int v = (idx < TN) ? g_cnt[idx] : 0;
    s[threadIdx.x] = v;
    __syncthreads();
    for (int off = 1; off < 1024; off <<= 1) {
        int add = (threadIdx.x >= off) ? s[threadIdx.x - off] : 0;
        __syncthreads();
        s[threadIdx.x] += add;
        __syncthreads();
    }
    if (idx < TN) g_off[idx] = s[threadIdx.x] - v;      // exclusive within block
    if (threadIdx.x == 1023) g_bsum[blockIdx.x] = s[1023];
}

__global__ void scan2_kernel() {   // single block, 512 threads, NBLK sums
    __shared__ int s[512];
    int v = (threadIdx.x < NBLK) ? g_bsum[threadIdx.x] : 0;
    s[threadIdx.x] = v;
    __syncthreads();
    for (int off = 1; off < 512; off <<= 1) {
        int add = (threadIdx.x >= off) ? s[threadIdx.x - off] : 0;
        __syncthreads();
        s[threadIdx.x] += add;
        __syncthreads();
    }
    if (threadIdx.x < NBLK) g_bsum[threadIdx.x] = s[threadIdx.x] - v;  // exclusive
}

__global__ void scan3_kernel() {
    int i = blockIdx.x * blockDim.x + threadIdx.x;
    if (i < TN) {
        int o = g_off[i] + g_bsum[i >> 10];
        g_off[i] = o;
        g_cur[i] = o;
    }
}

__global__ void scatter_kernel(const int* __restrict__ ei) {
    int e = blockIdx.x * blockDim.x + threadIdx.x;
    int t = blockIdx.y;
    if (e >= EE) return;
    const int* b = ei + (size_t)t * 2 * EE;
    int src = __ldg(b + e);
    int dst = __ldg(b + EE + e);
    int pos = atomicAdd(&g_cur[t * NN + dst], 1);
    g_csr[pos] = src;
}

// ---------------- layer 0: build x from inputs, project, write rows ----------------
__global__ void node0_kernel(const int* __restrict__ nt,
                             const float* __restrict__ req,
                             const float* __restrict__ ti,
                             const float* __restrict__ emb,
                             const float* __restrict__ W,
                             const float* __restrict__ as_,
                             const float* __restrict__ ad_) {
    __shared__ float sW[5 * 12];
    __shared__ float sas[12], sad[12];
    for (int i = threadIdx.x; i < 5 * 12; i += blockDim.x) sW[i] = W[i];
    if (threadIdx.x < 12) { sas[threadIdx.x] = as_[threadIdx.x]; sad[threadIdx.x] = ad_[threadIdx.x]; }
    __syncthreads();
    int idx = blockIdx.x * blockDim.x + threadIdx.x;
    if (idx >= TN) return;
    int t = idx / NN;
    int n = idx - t * NN;
    float mean = g_stats[2 * t], rstd = g_stats[2 * t + 1];
    int type = nt[idx];
    float r = req[idx];
    float xv[5];
    xv[0] = __ldg(&emb[type * 3 + 0]);
    xv[1] = __ldg(&emb[type * 3 + 1]);
    xv[2] = __ldg(&emb[type * 3 + 2]);
    xv[3] = (n < NLOCK) ? r : (r - mean) * rstd;
    xv[4] = ti[idx];

    float h[12];
    #pragma unroll
    for (int j = 0; j < 12; j++) {
        float a = 0.f;
        #pragma unroll
        for (int k = 0; k < 5; k++) a = fmaf(xv[k], sW[k * 12 + j], a);
        h[j] = a;
    }
    float es0 = 0.f, es1 = 0.f, ed0 = 0.f, ed1 = 0.f;
    #pragma unroll
    for (int c = 0; c < 6; c++) {
        es0 = fmaf(h[c],     sas[c],     es0);
        es1 = fmaf(h[6 + c], sas[6 + c], es1);
        ed0 = fmaf(h[c],     sad[c],     ed0);
        ed1 = fmaf(h[6 + c], sad[6 + c], ed1);
    }
    float4* row = &g_hsA[(size_t)idx * 4];
    row[0] = make_float4(es0, es1, ed0, ed1);
    row[1] = make_float4(h[0], h[1], h[2],  h[3]);
    row[2] = make_float4(h[4], h[5], h[6],  h[7]);
    row[3] = make_float4(h[8], h[9], h[10], h[11]);
}

// ---------------- fused gather + softmax + (bias/relu) + next projection ----------------
// 4 lanes per node. Grid is exactly TN*4 threads (no partial warps).
template <bool FINAL, bool A_TO_B>
__global__ void gather_kernel(const float* __restrict__ bcur,
                              const float* __restrict__ Wn,
                              const float* __restrict__ asn,
                              const float* __restrict__ adn,
                              float* __restrict__ outp) {
    __shared__ float sW[144], sas[12], sad[12], sb[12];
    if (!FINAL) {
        for (int k = threadIdx.x; k < 144; k += blockDim.x) sW[k] = Wn[k];
        if (threadIdx.x < 12) { sas[threadIdx.x] = asn[threadIdx.x]; sad[threadIdx.x] = adn[threadIdx.x]; }
    }
    if (threadIdx.x < 12) sb[threadIdx.x] = bcur[threadIdx.x];
    __syncthreads();

    const float4* hs_in = A_TO_B ? g_hsA : g_hsB;
    float4*       hs_out = A_TO_B ? g_hsB : g_hsA;

    int gt   = blockIdx.x * blockDim.x + threadIdx.x;
    int i    = gt >> 2;
    int lane = gt & 3;
    int t    = i / NN;
    const float4* tbase = hs_in + (size_t)t * NN * 4;

    float4 row0 = hs_in[(size_t)i * 4];
    float ed0 = row0.z, ed1 = row0.w;

    float acc[14];
    #pragma unroll
    for (int k = 0; k < 14; k++) acc[k] = 0.f;

    // self loop handled by lane 0
    if (lane == 0) {
        float p0 = __expf(lrelu(row0.x + ed0));
        float p1 = __expf(lrelu(row0.y + ed1));
        const float4* r = &hs_in[(size_t)i * 4];
        float4 h0 = r[1], h1 = r[2], h2 = r[3];
        acc[0] += h0.x * p0; acc[1] += h0.y * p0; acc[2]  += h0.z * p0; acc[3]  += h0.w * p0;
        acc[4] += h1.x * p0; acc[5] += h1.y * p0; acc[6]  += h1.z * p1; acc[7]  += h1.w * p1;
        acc[8] += h2.x * p1; acc[9] += h2.y * p1; acc[10] += h2.z * p1; acc[11] += h2.w * p1;
        acc[12] += p0; acc[13] += p1;
    }

    int beg = g_off[i], end = beg + g_cnt[i];
    for (int j = beg + lane; j < end; j += 4) {
        int src = g_csr[j];
        const float4* r = tbase + (size_t)src * 4;
        float4 s0 = r[0];
        float p0 = __expf(lrelu(s0.x + ed0));
        float p1 = __expf(lrelu(s0.y + ed1));
        float4 h0 = r[1], h1 = r[2], h2 = r[3];
        acc[0] += h0.x * p0; acc[1] += h0.y * p0; acc[2]  += h0.z * p0; acc[3]  += h0.w * p0;
        acc[4] += h1.x * p0; acc[5] += h1.y * p0; acc[6]  += h1.z * p1; acc[7]  += h1.w * p1;
        acc[8] += h2.x * p1; acc[9] += h2.y * p1; acc[10] += h2.z * p1; acc[11] += h2.w * p1;
        acc[12] += p0; acc[13] += p1;
    }

    // butterfly reduce across the quad (quads never straddle warps)
    #pragma unroll
    for (int k = 0; k < 14; k++) {
        acc[k] += __shfl_xor_sync(0xFFFFFFFFu, acc[k], 1);
        acc[k] += __shfl_xor_sync(0xFFFFFFFFu, acc[k], 2);
    }

    float r0 = 1.f / (acc[12] + 1e-16f);
    float r1 = 1.f / (acc[13] + 1e-16f);
    float o[12];
    #pragma unroll
    for (int k = 0; k < 12; k++) {
        float v = acc[k] * ((k < 6) ? r0 : r1) + sb[k];
        o[k] = FINAL ? v : fmaxf(v, 0.f);
    }

    if (FINAL) {
        if (lane < 3) {
            float4* dp = (float4*)(outp + (size_t)i * 12);
            dp[lane] = make_float4(o[lane * 4], o[lane * 4 + 1], o[lane * 4 + 2], o[lane * 4 + 3]);
        }
    } else {
        float hreg[4] = {0.f, 0.f, 0.f, 0.f};
        float es0 = 0.f, es1 = 0.f, ep0 = 0.f, ep1 = 0.f;
        if (lane < 3) {
            #pragma unroll
            for (int jj = 0; jj < 4; jj++) {
                int j = lane * 4 + jj;
                float a = 0.f;
                #pragma unroll
                for (int k = 0; k < 12; k++) a = fmaf(o[k], sW[k * 12 + j], a);
                hreg[jj] = a;
                if (j < 6) { es0 = fmaf(a, sas[j], es0); ep0 = fmaf(a, sad[j], ep0); }
                else       { es1 = fmaf(a, sas[j], es1); ep1 = fmaf(a, sad[j], ep1); }
            }
        }
        es0 += __shfl_xor_sync(0xFFFFFFFFu, es0, 1); es0 += __shfl_xor_sync(0xFFFFFFFFu, es0, 2);
        es1 += __shfl_xor_sync(0xFFFFFFFFu, es1, 1); es1 += __shfl_xor_sync(0xFFFFFFFFu, es1, 2);
        ep0 += __shfl_xor_sync(0xFFFFFFFFu, ep0, 1); ep0 += __shfl_xor_sync(0xFFFFFFFFu, ep0, 2);
        ep1 += __shfl_xor_sync(0xFFFFFFFFu, ep1, 1); ep1 += __shfl_xor_sync(0xFFFFFFFFu, ep1, 2);

        float4* row = &hs_out[(size_t)i * 4];
        if (lane == 3) row[0] = make_float4(es0, es1, ep0, ep1);
        else           row[1 + lane] = make_float4(hreg[0], hreg[1], hreg[2], hreg[3]);
    }
}

// ---------------- launch ----------------
extern "C" void kernel_launch(void* const* d_in, const int* in_sizes, int n_in,
                              void* d_out, int out_size) {
    const int*   node_types = (const int*)d_in[0];
    const float* requests   = (const float*)d_in[1];
    const float* time_index = (const float*)d_in[2];
    const int*   edge_index = (const int*)d_in[3];
    const float* emb        = (const float*)d_in[4];
    float* out = (float*)d_out;

    const int BT = 256;
    const int node_blocks = (TN + BT - 1) / BT;         // 1563
    dim3 e_grid(EE / BT, TT);                           // 6250 x 4
    const int gather_blocks = (TN * 4) / BT;            // 6250 exact

    // stats
    zero_stats_kernel<<<1, 32>>>();
    { dim3 grid(128, TT); reduce_req_kernel<<<grid, BT>>>(requests); }
    finalize_stats_kernel<<<1, 32>>>();

    // CSR build (once; reused by all 4 layers)
    zero_cnt_kernel<<<node_blocks, BT>>>();
    hist_kernel<<<e_grid, BT>>>(edge_index);
    scan1_kernel<<<NBLK, 1024>>>();
    scan2_kernel<<<1, 512>>>();
    scan3_kernel<<<node_blocks, BT>>>();
    scatter_kernel<<<e_grid, BT>>>(edge_index);

    // layer 0 projection
    node0_kernel<<<node_blocks, BT>>>(node_types, requests, time_index, emb,
                                      (const float*)d_in[5], (const float*)d_in[6],
                                      (const float*)d_in[7]);

    // layer 0 aggregate -> project layer1   (A -> B)
    gather_kernel<false, true ><<<gather_blocks, BT>>>(
        (const float*)d_in[8],  (const float*)d_in[9],
        (const float*)d_in[10], (const float*)d_in[11], nullptr);
    // layer 1 aggregate -> project layer2   (B -> A)
    gather_kernel<false, false><<<gather_blocks, BT>>>(
        (const float*)d_in[12], (const float*)d_in[13],
        (const float*)d_in[14], (const float*)d_in[15], nullptr);
    // layer 2 aggregate -> project layer3   (A -> B)
    gather_kernel<false, true ><<<gather_blocks, BT>>>(
        (const float*)d_in[16], (const float*)d_in[17],
        (const float*)d_in[18], (const float*)d_in[19], nullptr);
    // layer 3 aggregate -> output           (B -> out)
    gather_kernel<true,  false><<<gather_blocks, BT>>>(
        (const float*)d_in[20], nullptr, nullptr, nullptr, out);
}

// round 4
// speedup vs baseline: 3.5170x; 1.4863x over previous
#include <cuda_runtime.h>
#include <cuda_fp16.h>
#include <math.h>

#define NN 100000
#define EE 1600000
#define TT 4
#define NLOCK 15
#define TN (TT * NN)
#define NBLK 391          // ceil(TN / 1024)

// ---------------- static device scratch ----------------
// Node row, 32B = 1 L2 sector: [es0, es1 (fp32), h0..h11 (fp16)]
// stored as 2x float4 per node.
__device__ float4 g_rowA[TN * 2];
__device__ float4 g_rowB[TN * 2];
__device__ float2 g_edA[TN];
__device__ float2 g_edB[TN];
__device__ int    g_cnt[TN];
__device__ int    g_off[TN];
__device__ int    g_cur[TN];
__device__ int    g_bsum[512];
__device__ int    g_csr[TT * EE];
__device__ double g_sum[TT];
__device__ double g_sumsq[TT];
__device__ float  g_stats[TT * 2];

__device__ __forceinline__ float lrelu(float x) { return x > 0.f ? x : 0.2f * x; }

__device__ __forceinline__ float2 up2(float f) {
    unsigned u = __float_as_uint(f);
    __half2 h = *reinterpret_cast<__half2*>(&u);
    return __half22float2(h);
}
__device__ __forceinline__ float pk2(float a, float b) {
    __half2 h = __floats2half2_rn(a, b);
    return __uint_as_float(*reinterpret_cast<unsigned*>(&h));
}

// ---------------- stats: mean/std (ddof=1) of requests[t, 15:] ----------------
__global__ void zero_stats_kernel() {
    int i = threadIdx.x;
    if (i < TT) { g_sum[i] = 0.0; g_sumsq[i] = 0.0; }
}

__global__ void reduce_req_kernel(const float* __restrict__ req) {
    const int t = blockIdx.y;
    const int M = NN - NLOCK;
    double s = 0.0, ss = 0.0;
    for (int i = blockIdx.x * blockDim.x + threadIdx.x; i < M; i += gridDim.x * blockDim.x) {
        double v = (double)req[t * NN + NLOCK + i];
        s += v; ss += v * v;
    }
    #pragma unroll
    for (int o = 16; o > 0; o >>= 1) {
        s  += __shfl_down_sync(0xFFFFFFFFu, s,  o);
        ss += __shfl_down_sync(0xFFFFFFFFu, ss, o);
    }
    __shared__ double shs[8], shss[8];
    int w = threadIdx.x >> 5, l = threadIdx.x & 31;
    if (l == 0) { shs[w] = s; shss[w] = ss; }
    __syncthreads();
    if (threadIdx.x == 0) {
        double S = 0.0, SS = 0.0;
        int nw = blockDim.x >> 5;
        for (int i = 0; i < nw; i++) { S += shs[i]; SS += shss[i]; }
        atomicAdd(&g_sum[t], S);
        atomicAdd(&g_sumsq[t], SS);
    }
}

__global__ void finalize_stats_kernel() {
    int t = threadIdx.x;
    if (t < TT) {
        double n = (double)(NN - NLOCK);
        double mean = g_sum[t] / n;
        double var = (g_sumsq[t] - g_sum[t] * mean) / (n - 1.0);
        g_stats[2 * t]     = (float)mean;
        g_stats[2 * t + 1] = (float)(1.0 / sqrt(var));
    }
}

// ---------------- CSR build ----------------
__global__ void zero_cnt_kernel() {
    int i = blockIdx.x * blockDim.x + threadIdx.x;
    if (i < TN) g_cnt[i] = 0;
}

__global__ void hist_kernel(const int* __restrict__ ei) {
    int e = blockIdx.x * blockDim.x + threadIdx.x;
    int t = blockIdx.y;
    if (e >= EE) return;
    int dst = __ldg(ei + (size_t)t * 2 * EE + EE + e);
    atomicAdd(&g_cnt[t * NN + dst], 1);
}

__global__ void scan1_kernel() {
    __shared__ int s[1024];
    int idx = blockIdx.x * 1024 + threadIdx.x;
    int v = (idx < TN) ? g_cnt[idx] : 0;
    s[threadIdx.x] = v;
    __syncthreads();
    for (int off = 1; off < 1024; off <<= 1) {
        int add = (threadIdx.x >= off) ? s[threadIdx.x - off] : 0;
        __syncthreads();
        s[threadIdx.x] += add;
        __syncthreads();
    }
    if (idx < TN) g_off[idx] = s[threadIdx.x] - v;
    if (threadIdx.x == 1023) g_bsum[blockIdx.x] = s[1023];
}

__global__ void scan2_kernel() {
    __shared__ int s[512];
    int v = (threadIdx.x < NBLK) ? g_bsum[threadIdx.x] : 0;
    s[threadIdx.x] = v;
    __syncthreads();
    for (int off = 1; off < 512; off <<= 1) {
        int add = (threadIdx.x >= off) ? s[threadIdx.x - off] : 0;
        __syncthreads();
        s[threadIdx.x] += add;
        __syncthreads();
    }
    if (threadIdx.x < NBLK) g_bsum[threadIdx.x] = s[threadIdx.x] - v;
}

__global__ void scan3_kernel() {
    int i = blockIdx.x * blockDim.x + threadIdx.x;
    if (i < TN) {
        int o = g_off[i] + g_bsum[i >> 10];
        g_off[i] = o;
        g_cur[i] = o;
    }
}

__global__ void scatter_kernel(const int* __restrict__ ei) {
    int e = blockIdx.x * blockDim.x + threadIdx.x;
    int t = blockIdx.y;
    if (e >= EE) return;
    const int* b = ei + (size_t)t * 2 * EE;
    int src = __ldg(b + e);
    int dst = __ldg(b + EE + e);
    int pos = atomicAdd(&g_cur[t * NN + dst], 1);
    g_csr[pos] = src;
}

// ---------------- layer 0: build x from inputs, project, write rows ----------------
__global__ void node0_kernel(const int* __restrict__ nt,
                             const float* __restrict__ req,
                             const float* __restrict__ ti,
                             const float* __restrict__ emb,
                             const float* __restrict__ W,
                             const float* __restrict__ as_,
                             const float* __restrict__ ad_) {
    __shared__ float sW[5 * 12];
    __shared__ float sas[12], sad[12];
    for (int i = threadIdx.x; i < 5 * 12; i += blockDim.x) sW[i] = W[i];
    if (threadIdx.x < 12) { sas[threadIdx.x] = as_[threadIdx.x]; sad[threadIdx.x] = ad_[threadIdx.x]; }
    __syncthreads();
    int idx = blockIdx.x * blockDim.x + threadIdx.x;
    if (idx >= TN) return;
    int t = idx / NN;
    int n = idx - t * NN;
    float mean = g_stats[2 * t], rstd = g_stats[2 * t + 1];
    int type = nt[idx];
    float r = req[idx];
    float xv[5];
    xv[0] = __ldg(&emb[type * 3 + 0]);
    xv[1] = __ldg(&emb[type * 3 + 1]);
    xv[2] = __ldg(&emb[type * 3 + 2]);
    xv[3] = (n < NLOCK) ? r : (r - mean) * rstd;
    xv[4] = ti[idx];

    float h[12];
    #pragma unroll
    for (int j = 0; j < 12; j++) {
        float a = 0.f;
        #pragma unroll
        for (int k = 0; k < 5; k++) a = fmaf(xv[k], sW[k * 12 + j], a);
        h[j] = a;
    }
    float es0 = 0.f, es1 = 0.f, ed0 = 0.f, ed1 = 0.f;
    #pragma unroll
    for (int c = 0; c < 6; c++) {
        es0 = fmaf(h[c],     sas[c],     es0);
        es1 = fmaf(h[6 + c], sas[6 + c], es1);
        ed0 = fmaf(h[c],     sad[c],     ed0);
        ed1 = fmaf(h[6 + c], sad[6 + c], ed1);
    }
    g_rowA[(size_t)idx * 2]     = make_float4(es0, es1, pk2(h[0], h[1]), pk2(h[2], h[3]));
    g_rowA[(size_t)idx * 2 + 1] = make_float4(pk2(h[4], h[5]), pk2(h[6], h[7]),
                                              pk2(h[8], h[9]), pk2(h[10], h[11]));
    g_edA[idx] = make_float2(ed0, ed1);
}

// ---------------- fused gather + softmax + (bias/relu) + next projection ----------------
// 4 lanes per node; quads never straddle warps.
template <bool FINAL, bool A_TO_B>
__global__ void gather_kernel(const float* __restrict__ bcur,
                              const float* __restrict__ Wn,
                              const float* __restrict__ asn,
                              const float* __restrict__ adn,
                              float* __restrict__ outp) {
    __shared__ float sW[144], sas[12], sad[12], sb[12];
    if (!FINAL) {
        for (int k = threadIdx.x; k < 144; k += blockDim.x) sW[k] = Wn[k];
        if (threadIdx.x < 12) { sas[threadIdx.x] = asn[threadIdx.x]; sad[threadIdx.x] = adn[threadIdx.x]; }
    }
    if (threadIdx.x < 12) sb[threadIdx.x] = bcur[threadIdx.x];
    __syncthreads();

    const float4* rows_in = A_TO_B ? g_rowA : g_rowB;
    const float2* ed_in   = A_TO_B ? g_edA  : g_edB;
    float4*       rows_out = A_TO_B ? g_rowB : g_rowA;
    float2*       ed_out   = A_TO_B ? g_edB  : g_edA;

    int gt   = blockIdx.x * blockDim.x + threadIdx.x;
    int i    = gt >> 2;
    int lane = gt & 3;
    int t    = i / NN;
    const float4* tbase = rows_in + (size_t)t * NN * 2;

    float2 edv = ed_in[i];
    float ed0 = edv.x, ed1 = edv.y;

    float acc[14];
    #pragma unroll
    for (int k = 0; k < 14; k++) acc[k] = 0.f;

    // self loop handled by lane 0
    if (lane == 0) {
        float4 q0 = rows_in[(size_t)i * 2];
        float4 q1 = rows_in[(size_t)i * 2 + 1];
        float p0 = __expf(lrelu(q0.x + ed0));
        float p1 = __expf(lrelu(q0.y + ed1));
        float2 a = up2(q0.z), b = up2(q0.w), c = up2(q1.x);
        float2 d = up2(q1.y), e = up2(q1.z), f = up2(q1.w);
        acc[0] += a.x * p0; acc[1] += a.y * p0; acc[2]  += b.x * p0; acc[3]  += b.y * p0;
        acc[4] += c.x * p0; acc[5] += c.y * p0; acc[6]  += d.x * p1; acc[7]  += d.y * p1;
        acc[8] += e.x * p1; acc[9] += e.y * p1; acc[10] += f.x * p1; acc[11] += f.y * p1;
        acc[12] += p0; acc[13] += p1;
    }

    int beg = g_off[i], end = beg + g_cnt[i];
    #pragma unroll 2
    for (int j = beg + lane; j < end; j += 4) {
        int src = g_csr[j];
        float4 q0 = tbase[(size_t)src * 2];
        float4 q1 = tbase[(size_t)src * 2 + 1];
        float p0 = __expf(lrelu(q0.x + ed0));
        float p1 = __expf(lrelu(q0.y + ed1));
        float2 a = up2(q0.z), b = up2(q0.w), c = up2(q1.x);
        float2 d = up2(q1.y), e = up2(q1.z), f = up2(q1.w);
        acc[0] += a.x * p0; acc[1] += a.y * p0; acc[2]  += b.x * p0; acc[3]  += b.y * p0;
        acc[4] += c.x * p0; acc[5] += c.y * p0; acc[6]  += d.x * p1; acc[7]  += d.y * p1;
        acc[8] += e.x * p1; acc[9] += e.y * p1; acc[10] += f.x * p1; acc[11] += f.y * p1;
        acc[12] += p0; acc[13] += p1;
    }

    // butterfly reduce across the quad
    #pragma unroll
    for (int k = 0; k < 14; k++) {
        acc[k] += __shfl_xor_sync(0xFFFFFFFFu, acc[k], 1);
        acc[k] += __shfl_xor_sync(0xFFFFFFFFu, acc[k], 2);
    }

    float r0 = 1.f / (acc[12] + 1e-16f);
    float r1 = 1.f / (acc[13] + 1e-16f);
    float o[12];
    #pragma unroll
    for (int k = 0; k < 12; k++) {
        float v = acc[k] * ((k < 6) ? r0 : r1) + sb[k];
        o[k] = FINAL ? v : fmaxf(v, 0.f);
    }

    if (FINAL) {
        if (lane < 3) {
            float4* dp = (float4*)(outp + (size_t)i * 12);
            dp[lane] = make_float4(o[lane * 4], o[lane * 4 + 1], o[lane * 4 + 2], o[lane * 4 + 3]);
        }
    } else {
        float hreg[4] = {0.f, 0.f, 0.f, 0.f};
        float es0 = 0.f, es1 = 0.f, ep0 = 0.f, ep1 = 0.f;
        if (lane < 3) {
            #pragma unroll
            for (int jj = 0; jj < 4; jj++) {
                int j = lane * 4 + jj;
                float a = 0.f;
                #pragma unroll
                for (int k = 0; k < 12; k++) a = fmaf(o[k], sW[k * 12 + j], a);
                hreg[jj] = a;
                if (j < 6) { es0 = fmaf(a, sas[j], es0); ep0 = fmaf(a, sad[j], ep0); }
                else       { es1 = fmaf(a, sas[j], es1); ep1 = fmaf(a, sad[j], ep1); }
            }
        }
        es0 += __shfl_xor_sync(0xFFFFFFFFu, es0, 1); es0 += __shfl_xor_sync(0xFFFFFFFFu, es0, 2);
        es1 += __shfl_xor_sync(0xFFFFFFFFu, es1, 1); es1 += __shfl_xor_sync(0xFFFFFFFFu, es1, 2);
        ep0 += __shfl_xor_sync(0xFFFFFFFFu, ep0, 1); ep0 += __shfl_xor_sync(0xFFFFFFFFu, ep0, 2);
        ep1 += __shfl_xor_sync(0xFFFFFFFFu, ep1, 1); ep1 += __shfl_xor_sync(0xFFFFFFFFu, ep1, 2);

        float2* rowp = (float2*)&rows_out[(size_t)i * 2];
        if (lane == 3) {
            rowp[0] = make_float2(es0, es1);
            ed_out[i] = make_float2(ep0, ep1);
        } else {
            rowp[1 + lane] = make_float2(pk2(hreg[0], hreg[1]), pk2(hreg[2], hreg[3]));
        }
    }
}

// ---------------- launch ----------------
extern "C" void kernel_launch(void* const* d_in, const int* in_sizes, int n_in,
                              void* d_out, int out_size) {
    const int*   node_types = (const int*)d_in[0];
    const float* requests   = (const float*)d_in[1];
    const float* time_index = (const float*)d_in[2];
    const int*   edge_index = (const int*)d_in[3];
    const float* emb        = (const float*)d_in[4];
    float* out = (float*)d_out;

    const int BT = 256;
    const int node_blocks = (TN + BT - 1) / BT;
    dim3 e_grid(EE / BT, TT);
    const int gather_blocks = (TN * 4) / BT;

    zero_stats_kernel<<<1, 32>>>();
    { dim3 grid(128, TT); reduce_req_kernel<<<grid, BT>>>(requests); }
    finalize_stats_kernel<<<1, 32>>>();

    zero_cnt_kernel<<<node_blocks, BT>>>();
    hist_kernel<<<e_grid, BT>>>(edge_index);
    scan1_kernel<<<NBLK, 1024>>>();
    scan2_kernel<<<1, 512>>>();
    scan3_kernel<<<node_blocks, BT>>>();
    scatter_kernel<<<e_grid, BT>>>(edge_index);

    node0_kernel<<<node_blocks, BT>>>(node_types, requests, time_index, emb,
                                      (const float*)d_in[5], (const float*)d_in[6],
                                      (const float*)d_in[7]);

    gather_kernel<false, true ><<<gather_blocks, BT>>>(
        (const float*)d_in[8],  (const float*)d_in[9],
        (const float*)d_in[10], (const float*)d_in[11], nullptr);
    gather_kernel<false, false><<<gather_blocks, BT>>>(
        (const float*)d_in[12], (const float*)d_in[13],
        (const float*)d_in[14], (const float*)d_in[15], nullptr);
    gather_kernel<false, true ><<<gather_blocks, BT>>>(
        (const float*)d_in[16], (const float*)d_in[17],
        (const float*)d_in[18], (const float*)d_in[19], nullptr);
    gather_kernel<true,  false><<<gather_blocks, BT>>>(
        (const float*)d_in[20], nullptr, nullptr, nullptr, out);
}